// round 3
// baseline (speedup 1.0000x reference)
#include <cuda_runtime.h>
#include <mma.h>

using namespace nvcuda;

#define N_CONS 10000
#define N_COLS 10000
#define NN     20000
#define NE     200000
#define NE2    (NE + NN)        // edges + self loops = 220000
#define NEG_SLOPE 0.2f

// ---------------- scratch (static __device__ globals; no allocs) ------------
__device__ float g_emb0[(size_t)NN * 128];
__device__ float g_xp1 [(size_t)NN * 1024];
__device__ float g_emb1[(size_t)NN * 1024];
__device__ float g_xp2 [(size_t)NN * 128];
__device__ float g_emb2[(size_t)NN * 128];
__device__ float g_asrc[(size_t)NN * 8];
__device__ float g_adst[(size_t)NN * 8];
__device__ float g_alpha[(size_t)NE2 * 8];
__device__ int   g_deg[NN];
__device__ int   g_rowptr[NN + 1];
__device__ int   g_wpos[NN];
__device__ int   g_csrc[NE2];
__device__ int   g_is64;

__device__ __forceinline__ float to_tf32(float x)
{
    float r;
    asm("cvt.rna.tf32.f32 %0, %1;" : "=f"(r) : "f"(x));
    return r;
}

// ---------------- initial embedding ----------------------------------------
__global__ void k_embed(const float* __restrict__ cs, const float* __restrict__ co,
                        const float* __restrict__ nW, const float* __restrict__ nb,
                        const float* __restrict__ cW, const float* __restrict__ cb)
{
    int idx = blockIdx.x * blockDim.x + threadIdx.x;
    if (idx >= NN * 128) return;
    int n = idx >> 7, k = idx & 127;
    float s;
    if (n < N_CONS) {
        s = nb[k];
        const float* x = cs + (size_t)n * 4;
        const float* w = nW + (size_t)k * 8;
#pragma unroll
        for (int j = 0; j < 8; j++) s += x[j & 3] * w[j];
    } else {
        int m = n - N_CONS;
        s = cb[k];
        const float* x = co + (size_t)m * 8;
        const float* w = cW + (size_t)k * 16;
#pragma unroll
        for (int j = 0; j < 16; j++) s += x[j & 7] * w[j];
    }
    g_emb0[idx] = fmaxf(s, 0.f);
}

// ---------------- 3xTF32 tensor-core GEMM: C[M,N] = A[M,K] @ W[N,K]^T -------
// BM=128, BN=128, BK=16; 8 warps in 2(M)x4(N); warp tile 64x32.
// Smem stride 20 floats (80B): conflict-free fragment loads, 16B-aligned.
#define SST 20
template <bool RELU, bool BIAS>
__global__ __launch_bounds__(256)
void k_gemm_tc(const float* __restrict__ A, const float* __restrict__ W,
               const float* __restrict__ bias, float* __restrict__ C,
               int M, int N, int K)
{
    __shared__ __align__(16) float Ah[128 * SST];
    __shared__ __align__(16) float Al[128 * SST];
    __shared__ __align__(16) float Bh[128 * SST];
    __shared__ __align__(16) float Bl[128 * SST];
    __shared__ __align__(16) float sbuf[8 * 256];

    const int tid = threadIdx.x;
    const int wid = tid >> 5, lane = tid & 31;
    const int wm = wid >> 2, wn = wid & 3;      // 2 x 4 warp grid
    const int m0 = blockIdx.y * 128, n0 = blockIdx.x * 128;

    wmma::fragment<wmma::accumulator, 16, 16, 8, float> acc[4][2];
#pragma unroll
    for (int i = 0; i < 4; i++)
#pragma unroll
        for (int j = 0; j < 2; j++) wmma::fill_fragment(acc[i][j], 0.f);

    for (int k0 = 0; k0 < K; k0 += 16) {
        // load A tile [128 x 16] and B tile [128 x 16], split hi/lo, STS.128
#pragma unroll
        for (int l = 0; l < 2; l++) {
            int idx = tid * 2 + l;          // 0..511 float4 slots
            int row = idx >> 2, c4 = (idx & 3) * 4;
            float4 av = (m0 + row < M)
                ? *(const float4*)(A + (size_t)(m0 + row) * K + k0 + c4)
                : make_float4(0.f, 0.f, 0.f, 0.f);
            float4 hv, lv;
            hv.x = to_tf32(av.x); lv.x = to_tf32(av.x - hv.x);
            hv.y = to_tf32(av.y); lv.y = to_tf32(av.y - hv.y);
            hv.z = to_tf32(av.z); lv.z = to_tf32(av.z - hv.z);
            hv.w = to_tf32(av.w); lv.w = to_tf32(av.w - hv.w);
            *(float4*)&Ah[row * SST + c4] = hv;
            *(float4*)&Al[row * SST + c4] = lv;

            float4 bv = *(const float4*)(W + (size_t)(n0 + row) * K + k0 + c4);
            hv.x = to_tf32(bv.x); lv.x = to_tf32(bv.x - hv.x);
            hv.y = to_tf32(bv.y); lv.y = to_tf32(bv.y - hv.y);
            hv.z = to_tf32(bv.z); lv.z = to_tf32(bv.z - hv.z);
            hv.w = to_tf32(bv.w); lv.w = to_tf32(bv.w - hv.w);
            *(float4*)&Bh[row * SST + c4] = hv;
            *(float4*)&Bl[row * SST + c4] = lv;
        }
        __syncthreads();

#pragma unroll
        for (int kk = 0; kk < 16; kk += 8) {
            wmma::fragment<wmma::matrix_b, 16, 16, 8, wmma::precision::tf32,
                           wmma::col_major> bh[2], bl[2];
#pragma unroll
            for (int j = 0; j < 2; j++) {
                int nb_ = wn * 32 + j * 16;
                wmma::load_matrix_sync(bh[j], &Bh[nb_ * SST + kk], SST);
                wmma::load_matrix_sync(bl[j], &Bl[nb_ * SST + kk], SST);
            }
#pragma unroll
            for (int i = 0; i < 4; i++) {
                int ma = wm * 64 + i * 16;
                wmma::fragment<wmma::matrix_a, 16, 16, 8, wmma::precision::tf32,
                               wmma::row_major> ah, al;
                wmma::load_matrix_sync(ah, &Ah[ma * SST + kk], SST);
                wmma::load_matrix_sync(al, &Al[ma * SST + kk], SST);
#pragma unroll
                for (int j = 0; j < 2; j++) {
                    wmma::mma_sync(acc[i][j], ah, bh[j], acc[i][j]);
                    wmma::mma_sync(acc[i][j], ah, bl[j], acc[i][j]);
                    wmma::mma_sync(acc[i][j], al, bh[j], acc[i][j]);
                }
            }
        }
        __syncthreads();
    }

    // epilogue: frag -> smem -> global with optional bias/relu
    float* sb = &sbuf[wid * 256];
#pragma unroll
    for (int i = 0; i < 4; i++) {
#pragma unroll
        for (int j = 0; j < 2; j++) {
            wmma::store_matrix_sync(sb, acc[i][j], 16, wmma::mem_row_major);
            __syncwarp();
#pragma unroll
            for (int e = 0; e < 8; e++) {
                int idx = e * 32 + lane;
                int r = idx >> 4, c = idx & 15;
                int m = m0 + wm * 64 + i * 16 + r;
                int n = n0 + wn * 32 + j * 16 + c;
                if (m < M) {
                    float v = sb[idx];
                    if (BIAS) v += bias[n];
                    if (RELU) v = fmaxf(v, 0.f);
                    C[(size_t)m * N + n] = v;
                }
            }
            __syncwarp();
        }
    }
}

// ---------------- attention logits per node: a_src, a_dst ------------------
__global__ void k_att(const float* __restrict__ xp, const float* __restrict__ asv,
                      const float* __restrict__ adv, int H)
{
    int wid  = (blockIdx.x * blockDim.x + threadIdx.x) >> 5;
    int lane = threadIdx.x & 31;
    if (wid >= NN * H) return;
    int n = wid / H, h = wid % H;
    const float* row = xp  + ((size_t)n * H + h) * 128;
    const float* as  = asv + (size_t)h * 128;
    const float* ad  = adv + (size_t)h * 128;
    float s = 0.f, d = 0.f;
#pragma unroll
    for (int c = lane; c < 128; c += 32) {
        float v = row[c];
        s += v * as[c];
        d += v * ad[c];
    }
#pragma unroll
    for (int o = 16; o; o >>= 1) {
        s += __shfl_xor_sync(~0u, s, o);
        d += __shfl_xor_sync(~0u, d, o);
    }
    if (lane == 0) { g_asrc[n * H + h] = s; g_adst[n * H + h] = d; }
}

// ---------------- CSR build (by destination; includes self loops) ----------
__global__ void k_detect64(const void* ed)
{
    if (blockIdx.x | threadIdx.x) return;
    const int* p = (const int*)ed;
    int all0 = 1;
    for (int i = 0; i < 32; i++) all0 &= (p[2 * i + 1] == 0);
    g_is64 = all0;
}
__global__ void k_deg_init()
{
    int i = blockIdx.x * blockDim.x + threadIdx.x;
    if (i < NN) g_deg[i] = 1;   // self loop
}
__global__ void k_count(const void* ed)
{
    int e = blockIdx.x * blockDim.x + threadIdx.x;
    if (e >= NE) return;
    int d = g_is64 ? (int)((const long long*)ed)[NE + e]
                   : ((const int*)ed)[NE + e];
    atomicAdd(&g_deg[d], 1);
}
// single-pass scan: 1024 threads x 20-elem serial chunks + shfl block scan
__global__ void k_scan()
{
    const int CH = 20;
    int tid = threadIdx.x, lane = tid & 31, w = tid >> 5;
    int base = tid * CH;
    int sum = 0;
#pragma unroll
    for (int j = 0; j < CH; j++) {
        int i = base + j;
        if (i < NN) sum += g_deg[i];
    }
    int incl = sum;
#pragma unroll
    for (int o = 1; o < 32; o <<= 1) {
        int t = __shfl_up_sync(~0u, incl, o);
        if (lane >= o) incl += t;
    }
    __shared__ int wsum[32];
    if (lane == 31) wsum[w] = incl;
    __syncthreads();
    if (w == 0) {
        int v = wsum[lane];
        int s = v;
#pragma unroll
        for (int o = 1; o < 32; o <<= 1) {
            int t = __shfl_up_sync(~0u, s, o);
            if (lane >= o) s += t;
        }
        wsum[lane] = s - v;
    }
    __syncthreads();
    int excl = wsum[w] + incl - sum;
    int running = excl;
#pragma unroll
    for (int j = 0; j < CH; j++) {
        int i = base + j;
        if (i < NN) {
            g_rowptr[i] = running;
            g_wpos[i]   = running;
            running += g_deg[i];
        }
    }
    if (base < NN && base + CH >= NN) g_rowptr[NN] = running;
}
__global__ void k_scatter(const void* ed)
{
    int e = blockIdx.x * blockDim.x + threadIdx.x;
    if (e >= NE2) return;
    int s, d;
    if (e < NE) {
        if (g_is64) { s = (int)((const long long*)ed)[e]; d = (int)((const long long*)ed)[NE + e]; }
        else        { s = ((const int*)ed)[e];            d = ((const int*)ed)[NE + e]; }
    } else {
        s = d = e - NE;
    }
    int p = atomicAdd(&g_wpos[d], 1);
    g_csrc[p] = s;
}

// ---------------- segment softmax over incoming edges (warp per dst,h) -----
__global__ void k_softmax(int H)
{
    int wid  = (blockIdx.x * blockDim.x + threadIdx.x) >> 5;
    int lane = threadIdx.x & 31;
    if (wid >= NN * H) return;
    int dst = wid / H, h = wid % H;
    int beg = g_rowptr[dst], end = g_rowptr[dst + 1];
    float ad = g_adst[dst * H + h];

    float m = -1e30f;
    for (int i = beg + lane; i < end; i += 32) {
        float e = g_asrc[g_csrc[i] * H + h] + ad;
        e = e > 0.f ? e : NEG_SLOPE * e;
        m = fmaxf(m, e);
    }
#pragma unroll
    for (int o = 16; o; o >>= 1) m = fmaxf(m, __shfl_xor_sync(~0u, m, o));

    float s = 0.f;
    for (int i = beg + lane; i < end; i += 32) {
        float e = g_asrc[g_csrc[i] * H + h] + ad;
        e = e > 0.f ? e : NEG_SLOPE * e;
        float p = __expf(e - m);
        g_alpha[(size_t)i * H + h] = p;
        s += p;
    }
#pragma unroll
    for (int o = 16; o; o >>= 1) s += __shfl_xor_sync(~0u, s, o);

    float inv = 1.f / (s + 1e-16f);
    for (int i = beg + lane; i < end; i += 32) g_alpha[(size_t)i * H + h] *= inv;
}

// ---------------- weighted aggregation (warp per dst,h; float4 lanes) ------
__global__ void k_agg(const float* __restrict__ xp, const float* __restrict__ bias,
                      float* __restrict__ out, int H)
{
    int wid  = (blockIdx.x * blockDim.x + threadIdx.x) >> 5;
    int lane = threadIdx.x & 31;
    if (wid >= NN * H) return;
    int dst = wid / H, h = wid % H;
    int beg = g_rowptr[dst], end = g_rowptr[dst + 1];

    float4 acc = make_float4(0.f, 0.f, 0.f, 0.f);
    for (int i = beg; i < end; i++) {
        int   s = g_csrc[i];
        float a = g_alpha[(size_t)i * H + h];
        float4 v = *(const float4*)(xp + ((size_t)s * H + h) * 128 + lane * 4);
        acc.x += a * v.x; acc.y += a * v.y; acc.z += a * v.z; acc.w += a * v.w;
    }
    const float* b = bias + (size_t)h * 128 + lane * 4;
    float4 r = make_float4(fmaxf(acc.x + b[0], 0.f), fmaxf(acc.y + b[1], 0.f),
                           fmaxf(acc.z + b[2], 0.f), fmaxf(acc.w + b[3], 0.f));
    *(float4*)(out + ((size_t)dst * H + h) * 128 + lane * 4) = r;
}

// ---------------- launch ----------------------------------------------------
extern "C" void kernel_launch(void* const* d_in, const int* in_sizes, int n_in,
                              void* d_out, int out_size)
{
    const float* cs    = (const float*)d_in[0];
    const float* co    = (const float*)d_in[1];
    const float* nW    = (const float*)d_in[2];
    const float* nb    = (const float*)d_in[3];
    const float* cW    = (const float*)d_in[4];
    const float* cb    = (const float*)d_in[5];
    const float* W1    = (const float*)d_in[6];
    const float* as1   = (const float*)d_in[7];
    const float* ad1   = (const float*)d_in[8];
    const float* b1    = (const float*)d_in[9];
    const float* W2    = (const float*)d_in[10];
    const float* as2   = (const float*)d_in[11];
    const float* ad2   = (const float*)d_in[12];
    const float* b2    = (const float*)d_in[13];
    const float* oW    = (const float*)d_in[14];
    const float* ob    = (const float*)d_in[15];
    const void*  edges = (const void*)d_in[16];
    float* out = (float*)d_out;

    float *p_emb0, *p_xp1, *p_emb1, *p_xp2, *p_emb2;
    cudaGetSymbolAddress((void**)&p_emb0, g_emb0);
    cudaGetSymbolAddress((void**)&p_xp1,  g_xp1);
    cudaGetSymbolAddress((void**)&p_emb1, g_emb1);
    cudaGetSymbolAddress((void**)&p_xp2,  g_xp2);
    cudaGetSymbolAddress((void**)&p_emb2, g_emb2);

    // ---- forked stream: CSR build overlaps embed + GEMM1 + att ----
    cudaStream_t s2;
    cudaStreamCreateWithFlags(&s2, cudaStreamNonBlocking);
    cudaEvent_t eFork, eJoin;
    cudaEventCreateWithFlags(&eFork, cudaEventDisableTiming);
    cudaEventCreateWithFlags(&eJoin, cudaEventDisableTiming);

    cudaEventRecord(eFork, 0);
    cudaStreamWaitEvent(s2, eFork, 0);
    k_detect64<<<1, 32, 0, s2>>>(edges);
    k_deg_init<<<(NN + 255) / 256, 256, 0, s2>>>();
    k_count<<<(NE + 255) / 256, 256, 0, s2>>>(edges);
    k_scan<<<1, 1024, 0, s2>>>();
    k_scatter<<<(NE2 + 255) / 256, 256, 0, s2>>>(edges);
    cudaEventRecord(eJoin, s2);

    // main stream: embeddings + GEMM1 + attention logits
    k_embed<<<(NN * 128 + 255) / 256, 256>>>(cs, co, nW, nb, cW, cb);
    k_gemm_tc<false, false><<<dim3(1024 / 128, (NN + 127) / 128), 256>>>(
        p_emb0, W1, nullptr, p_xp1, NN, 1024, 128);
    k_att<<<(NN * 8) / 8, 256>>>(p_xp1, as1, ad1, 8);

    // join CSR before softmax
    cudaStreamWaitEvent(0, eJoin, 0);

    k_softmax<<<(NN * 8) / 8, 256>>>(8);
    k_agg<<<(NN * 8) / 8, 256>>>(p_xp1, b1, p_emb1, 8);

    // ----- GAT layer 2 (H=1, C=128) -----
    k_gemm_tc<false, false><<<dim3(1, (NN + 127) / 128), 256>>>(
        p_emb1, W2, nullptr, p_xp2, NN, 128, 1024);
    k_att<<<(NN * 1 + 7) / 8, 256>>>(p_xp2, as2, ad2, 1);
    k_softmax<<<(NN * 1 + 7) / 8, 256>>>(1);
    k_agg<<<(NN * 1 + 7) / 8, 256>>>(p_xp2, b2, p_emb2, 1);

    // ----- logits = emb2[-N_COLS:] @ out_W^T + out_b -----
    k_gemm_tc<false, true><<<dim3(1, (N_COLS + 127) / 128), 256>>>(
        p_emb2 + (size_t)N_CONS * 128, oW, ob, out, N_COLS, 128, 128);
}

// round 5
// speedup vs baseline: 2.4035x; 2.4035x over previous
#include <cuda_runtime.h>
#include <cuda_bf16.h>
#include <mma.h>

using namespace nvcuda;

#define N_CONS 10000
#define N_COLS 10000
#define NN     20000
#define NE     200000
#define NE2    (NE + NN)        // edges + self loops = 220000
#define NEG_SLOPE 0.2f

// ---------------- scratch (static __device__ globals; no allocs) ------------
__device__ float g_emb0[(size_t)NN * 128];
__device__ float g_xp1 [(size_t)NN * 1024];
__device__ float g_emb1[(size_t)NN * 1024];
__device__ float g_xp2 [(size_t)NN * 128];
__device__ float g_emb2[(size_t)NN * 128];
__device__ float g_asrc[(size_t)NN * 8];
__device__ float g_adst[(size_t)NN * 8];
__device__ float g_alpha[(size_t)NE2 * 8];
__device__ int   g_deg[NN];
__device__ int   g_rowptr[NN + 1];
__device__ int   g_wpos[NN];
__device__ int   g_csrc[NE2];
__device__ int   g_is64;

// ---------------- initial embedding ----------------------------------------
__global__ void k_embed(const float* __restrict__ cs, const float* __restrict__ co,
                        const float* __restrict__ nW, const float* __restrict__ nb,
                        const float* __restrict__ cW, const float* __restrict__ cb)
{
    int idx = blockIdx.x * blockDim.x + threadIdx.x;
    if (idx >= NN * 128) return;
    int n = idx >> 7, k = idx & 127;
    float s;
    if (n < N_CONS) {
        s = nb[k];
        const float* x = cs + (size_t)n * 4;
        const float* w = nW + (size_t)k * 8;
#pragma unroll
        for (int j = 0; j < 8; j++) s += x[j & 3] * w[j];
    } else {
        int m = n - N_CONS;
        s = cb[k];
        const float* x = co + (size_t)m * 8;
        const float* w = cW + (size_t)k * 16;
#pragma unroll
        for (int j = 0; j < 16; j++) s += x[j & 7] * w[j];
    }
    g_emb0[idx] = fmaxf(s, 0.f);
}

// ---------------- bf16 3-MMA compensated GEMM: C = A[M,K] @ W[N,K]^T --------
// BM=128, BN=128, BK=32 (bf16). 8 warps 2(M)x4(N); warp tile 64x32.
// Smem row stride 40 bf16 (80B): 16B-aligned rows, fragment rows hit banks
// 20r mod 32 -> <=2-way conflicts. hi/lo split: acc += ah*bh + ah*bl + al*bh.
#define SST 40
__device__ __forceinline__ unsigned pk2(__nv_bfloat16 a, __nv_bfloat16 b)
{
    __nv_bfloat162 t; t.x = a; t.y = b;
    return *(unsigned*)&t;
}

template <bool RELU, bool BIAS>
__global__ __launch_bounds__(256, 1)
void k_gemm_tc(const float* __restrict__ A, const float* __restrict__ W,
               const float* __restrict__ bias, float* __restrict__ C,
               int M, int N, int K)
{
    __shared__ __align__(16) __nv_bfloat16 Ah[128 * SST];
    __shared__ __align__(16) __nv_bfloat16 Al[128 * SST];
    __shared__ __align__(16) __nv_bfloat16 Bh[128 * SST];
    __shared__ __align__(16) __nv_bfloat16 Bl[128 * SST];

    const int tid = threadIdx.x;
    const int wid = tid >> 5, lane = tid & 31;
    const int wm = wid >> 2, wn = wid & 3;      // 2 x 4 warp grid
    const int m0 = blockIdx.y * 128, n0 = blockIdx.x * 128;

    wmma::fragment<wmma::accumulator, 16, 16, 16, float> acc[4][2];
#pragma unroll
    for (int i = 0; i < 4; i++)
#pragma unroll
        for (int j = 0; j < 2; j++) wmma::fill_fragment(acc[i][j], 0.f);

    for (int k0 = 0; k0 < K; k0 += 32) {
        // each thread loads 2 groups of 8 contiguous floats for A and for W
#pragma unroll
        for (int l = 0; l < 2; l++) {
            int g = tid * 2 + l;                 // 0..511
            int row = g >> 2, c8 = (g & 3) * 8;
            const float* ap = A + (size_t)(m0 + row) * K + k0 + c8;
            float x[8];
            if (m0 + row < M) {
                float4 u = *(const float4*)ap, v = *(const float4*)(ap + 4);
                x[0]=u.x; x[1]=u.y; x[2]=u.z; x[3]=u.w;
                x[4]=v.x; x[5]=v.y; x[6]=v.z; x[7]=v.w;
            } else {
#pragma unroll
                for (int q = 0; q < 8; q++) x[q] = 0.f;
            }
            __nv_bfloat16 h[8], lo[8];
#pragma unroll
            for (int q = 0; q < 8; q++) {
                h[q]  = __float2bfloat16(x[q]);
                lo[q] = __float2bfloat16(x[q] - __bfloat162float(h[q]));
            }
            uint4 uh = make_uint4(pk2(h[0],h[1]), pk2(h[2],h[3]),
                                  pk2(h[4],h[5]), pk2(h[6],h[7]));
            uint4 ul = make_uint4(pk2(lo[0],lo[1]), pk2(lo[2],lo[3]),
                                  pk2(lo[4],lo[5]), pk2(lo[6],lo[7]));
            *(uint4*)&Ah[row * SST + c8] = uh;
            *(uint4*)&Al[row * SST + c8] = ul;

            const float* wp = W + (size_t)(n0 + row) * K + k0 + c8;
            float4 u = *(const float4*)wp, v = *(const float4*)(wp + 4);
            x[0]=u.x; x[1]=u.y; x[2]=u.z; x[3]=u.w;
            x[4]=v.x; x[5]=v.y; x[6]=v.z; x[7]=v.w;
#pragma unroll
            for (int q = 0; q < 8; q++) {
                h[q]  = __float2bfloat16(x[q]);
                lo[q] = __float2bfloat16(x[q] - __bfloat162float(h[q]));
            }
            uh = make_uint4(pk2(h[0],h[1]), pk2(h[2],h[3]),
                            pk2(h[4],h[5]), pk2(h[6],h[7]));
            ul = make_uint4(pk2(lo[0],lo[1]), pk2(lo[2],lo[3]),
                            pk2(lo[4],lo[5]), pk2(lo[6],lo[7]));
            *(uint4*)&Bh[row * SST + c8] = uh;
            *(uint4*)&Bl[row * SST + c8] = ul;
        }
        __syncthreads();

#pragma unroll
        for (int kk = 0; kk < 32; kk += 16) {
            wmma::fragment<wmma::matrix_b, 16, 16, 16, __nv_bfloat16,
                           wmma::col_major> bh[2], bl[2];
#pragma unroll
            for (int j = 0; j < 2; j++) {
                int nb_ = wn * 32 + j * 16;
                wmma::load_matrix_sync(bh[j], &Bh[nb_ * SST + kk], SST);
                wmma::load_matrix_sync(bl[j], &Bl[nb_ * SST + kk], SST);
            }
#pragma unroll
            for (int i = 0; i < 4; i++) {
                int ma = wm * 64 + i * 16;
                wmma::fragment<wmma::matrix_a, 16, 16, 16, __nv_bfloat16,
                               wmma::row_major> ah, al;
                wmma::load_matrix_sync(ah, &Ah[ma * SST + kk], SST);
                wmma::load_matrix_sync(al, &Al[ma * SST + kk], SST);
#pragma unroll
                for (int j = 0; j < 2; j++) {
                    wmma::mma_sync(acc[i][j], ah, bh[j], acc[i][j]);
                    wmma::mma_sync(acc[i][j], ah, bl[j], acc[i][j]);
                    wmma::mma_sync(acc[i][j], al, bh[j], acc[i][j]);
                }
            }
        }
        __syncthreads();
    }

    // epilogue: frag -> smem (reuse Ah) -> global with optional bias/relu
    float* sb = (float*)Ah + wid * 256;
#pragma unroll
    for (int i = 0; i < 4; i++) {
#pragma unroll
        for (int j = 0; j < 2; j++) {
            wmma::store_matrix_sync(sb, acc[i][j], 16, wmma::mem_row_major);
            __syncwarp();
#pragma unroll
            for (int e = 0; e < 8; e++) {
                int idx = e * 32 + lane;
                int r = idx >> 4, c = idx & 15;
                int m = m0 + wm * 64 + i * 16 + r;
                int n = n0 + wn * 32 + j * 16 + c;
                if (m < M) {
                    float v = sb[idx];
                    if (BIAS) v += bias[n];
                    if (RELU) v = fmaxf(v, 0.f);
                    C[(size_t)m * N + n] = v;
                }
            }
            __syncwarp();
        }
    }
}

// ---------------- attention logits per node: a_src, a_dst ------------------
__global__ void k_att(const float* __restrict__ xp, const float* __restrict__ asv,
                      const float* __restrict__ adv, int H)
{
    int wid  = (blockIdx.x * blockDim.x + threadIdx.x) >> 5;
    int lane = threadIdx.x & 31;
    if (wid >= NN * H) return;
    int n = wid / H, h = wid % H;
    const float* row = xp  + ((size_t)n * H + h) * 128;
    const float* as  = asv + (size_t)h * 128;
    const float* ad  = adv + (size_t)h * 128;
    float s = 0.f, d = 0.f;
#pragma unroll
    for (int c = lane; c < 128; c += 32) {
        float v = row[c];
        s += v * as[c];
        d += v * ad[c];
    }
#pragma unroll
    for (int o = 16; o; o >>= 1) {
        s += __shfl_xor_sync(~0u, s, o);
        d += __shfl_xor_sync(~0u, d, o);
    }
    if (lane == 0) { g_asrc[n * H + h] = s; g_adst[n * H + h] = d; }
}

// ---------------- CSR build (by destination; includes self loops) ----------
__global__ void k_detect64(const void* ed)
{
    if (blockIdx.x | threadIdx.x) return;
    const int* p = (const int*)ed;
    int all0 = 1;
    for (int i = 0; i < 32; i++) all0 &= (p[2 * i + 1] == 0);
    g_is64 = all0;
}
__global__ void k_deg_init()
{
    int i = blockIdx.x * blockDim.x + threadIdx.x;
    if (i < NN) g_deg[i] = 1;   // self loop
}
__global__ void k_count(const void* ed)
{
    int e = blockIdx.x * blockDim.x + threadIdx.x;
    if (e >= NE) return;
    int d = g_is64 ? (int)((const long long*)ed)[NE + e]
                   : ((const int*)ed)[NE + e];
    atomicAdd(&g_deg[d], 1);
}
// single-pass scan: 1024 threads x 20-elem serial chunks + shfl block scan
__global__ void k_scan()
{
    const int CH = 20;
    int tid = threadIdx.x, lane = tid & 31, w = tid >> 5;
    int base = tid * CH;
    int sum = 0;
#pragma unroll
    for (int j = 0; j < CH; j++) {
        int i = base + j;
        if (i < NN) sum += g_deg[i];
    }
    int incl = sum;
#pragma unroll
    for (int o = 1; o < 32; o <<= 1) {
        int t = __shfl_up_sync(~0u, incl, o);
        if (lane >= o) incl += t;
    }
    __shared__ int wsum[32];
    if (lane == 31) wsum[w] = incl;
    __syncthreads();
    if (w == 0) {
        int v = wsum[lane];
        int s = v;
#pragma unroll
        for (int o = 1; o < 32; o <<= 1) {
            int t = __shfl_up_sync(~0u, s, o);
            if (lane >= o) s += t;
        }
        wsum[lane] = s - v;
    }
    __syncthreads();
    int excl = wsum[w] + incl - sum;
    int running = excl;
#pragma unroll
    for (int j = 0; j < CH; j++) {
        int i = base + j;
        if (i < NN) {
            g_rowptr[i] = running;
            g_wpos[i]   = running;
            running += g_deg[i];
        }
    }
    if (base < NN && base + CH >= NN) g_rowptr[NN] = running;
}
__global__ void k_scatter(const void* ed)
{
    int e = blockIdx.x * blockDim.x + threadIdx.x;
    if (e >= NE2) return;
    int s, d;
    if (e < NE) {
        if (g_is64) { s = (int)((const long long*)ed)[e]; d = (int)((const long long*)ed)[NE + e]; }
        else        { s = ((const int*)ed)[e];            d = ((const int*)ed)[NE + e]; }
    } else {
        s = d = e - NE;
    }
    int p = atomicAdd(&g_wpos[d], 1);
    g_csrc[p] = s;
}

// ---------------- segment softmax over incoming edges (warp per dst,h) -----
__global__ void k_softmax(int H)
{
    int wid  = (blockIdx.x * blockDim.x + threadIdx.x) >> 5;
    int lane = threadIdx.x & 31;
    if (wid >= NN * H) return;
    int dst = wid / H, h = wid % H;
    int beg = g_rowptr[dst], end = g_rowptr[dst + 1];
    float ad = g_adst[dst * H + h];

    float m = -1e30f;
    for (int i = beg + lane; i < end; i += 32) {
        float e = g_asrc[g_csrc[i] * H + h] + ad;
        e = e > 0.f ? e : NEG_SLOPE * e;
        m = fmaxf(m, e);
    }
#pragma unroll
    for (int o = 16; o; o >>= 1) m = fmaxf(m, __shfl_xor_sync(~0u, m, o));

    float s = 0.f;
    for (int i = beg + lane; i < end; i += 32) {
        float e = g_asrc[g_csrc[i] * H + h] + ad;
        e = e > 0.f ? e : NEG_SLOPE * e;
        float p = __expf(e - m);
        g_alpha[(size_t)i * H + h] = p;
        s += p;
    }
#pragma unroll
    for (int o = 16; o; o >>= 1) s += __shfl_xor_sync(~0u, s, o);

    float inv = 1.f / (s + 1e-16f);
    for (int i = beg + lane; i < end; i += 32) g_alpha[(size_t)i * H + h] *= inv;
}

// ---------------- weighted aggregation (warp per dst,h; float4 lanes) ------
__global__ void k_agg(const float* __restrict__ xp, const float* __restrict__ bias,
                      float* __restrict__ out, int H)
{
    int wid  = (blockIdx.x * blockDim.x + threadIdx.x) >> 5;
    int lane = threadIdx.x & 31;
    if (wid >= NN * H) return;
    int dst = wid / H, h = wid % H;
    int beg = g_rowptr[dst], end = g_rowptr[dst + 1];

    float4 acc = make_float4(0.f, 0.f, 0.f, 0.f);
    for (int i = beg; i < end; i++) {
        int   s = g_csrc[i];
        float a = g_alpha[(size_t)i * H + h];
        float4 v = *(const float4*)(xp + ((size_t)s * H + h) * 128 + lane * 4);
        acc.x += a * v.x; acc.y += a * v.y; acc.z += a * v.z; acc.w += a * v.w;
    }
    const float* b = bias + (size_t)h * 128 + lane * 4;
    float4 r = make_float4(fmaxf(acc.x + b[0], 0.f), fmaxf(acc.y + b[1], 0.f),
                           fmaxf(acc.z + b[2], 0.f), fmaxf(acc.w + b[3], 0.f));
    *(float4*)(out + ((size_t)dst * H + h) * 128 + lane * 4) = r;
}

// ---------------- launch ----------------------------------------------------
extern "C" void kernel_launch(void* const* d_in, const int* in_sizes, int n_in,
                              void* d_out, int out_size)
{
    const float* cs    = (const float*)d_in[0];
    const float* co    = (const float*)d_in[1];
    const float* nW    = (const float*)d_in[2];
    const float* nb    = (const float*)d_in[3];
    const float* cW    = (const float*)d_in[4];
    const float* cb    = (const float*)d_in[5];
    const float* W1    = (const float*)d_in[6];
    const float* as1   = (const float*)d_in[7];
    const float* ad1   = (const float*)d_in[8];
    const float* b1    = (const float*)d_in[9];
    const float* W2    = (const float*)d_in[10];
    const float* as2   = (const float*)d_in[11];
    const float* ad2   = (const float*)d_in[12];
    const float* b2    = (const float*)d_in[13];
    const float* oW    = (const float*)d_in[14];
    const float* ob    = (const float*)d_in[15];
    const void*  edges = (const void*)d_in[16];
    float* out = (float*)d_out;

    float *p_emb0, *p_xp1, *p_emb1, *p_xp2, *p_emb2;
    cudaGetSymbolAddress((void**)&p_emb0, g_emb0);
    cudaGetSymbolAddress((void**)&p_xp1,  g_xp1);
    cudaGetSymbolAddress((void**)&p_emb1, g_emb1);
    cudaGetSymbolAddress((void**)&p_xp2,  g_xp2);
    cudaGetSymbolAddress((void**)&p_emb2, g_emb2);

    // CSR build (graph identical for both layers; flip only reorders edges)
    k_detect64<<<1, 32>>>(edges);
    k_deg_init<<<(NN + 255) / 256, 256>>>();
    k_count<<<(NE + 255) / 256, 256>>>(edges);
    k_scan<<<1, 1024>>>();
    k_scatter<<<(NE2 + 255) / 256, 256>>>(edges);

    // initial node/column embeddings
    k_embed<<<(NN * 128 + 255) / 256, 256>>>(cs, co, nW, nb, cW, cb);

    // ----- GAT layer 1 (H=8, C=128) -----
    k_gemm_tc<false, false><<<dim3(1024 / 128, (NN + 127) / 128), 256>>>(
        p_emb0, W1, nullptr, p_xp1, NN, 1024, 128);
    k_att<<<(NN * 8) / 8, 256>>>(p_xp1, as1, ad1, 8);
    k_softmax<<<(NN * 8) / 8, 256>>>(8);
    k_agg<<<(NN * 8) / 8, 256>>>(p_xp1, b1, p_emb1, 8);

    // ----- GAT layer 2 (H=1, C=128) -----
    k_gemm_tc<false, false><<<dim3(1, (NN + 127) / 128), 256>>>(
        p_emb1, W2, nullptr, p_xp2, NN, 128, 1024);
    k_att<<<(NN * 1 + 7) / 8, 256>>>(p_xp2, as2, ad2, 1);
    k_softmax<<<(NN * 1 + 7) / 8, 256>>>(1);
    k_agg<<<(NN * 1 + 7) / 8, 256>>>(p_xp2, b2, p_emb2, 1);

    // ----- logits = emb2[-N_COLS:] @ out_W^T + out_b -----
    k_gemm_tc<false, true><<<dim3(1, (N_COLS + 127) / 128), 256>>>(
        p_emb2 + (size_t)N_CONS * 128, oW, ob, out, N_COLS, 128, 128);
}

// round 6
// speedup vs baseline: 2.7772x; 1.1554x over previous
#include <cuda_runtime.h>
#include <cuda_bf16.h>
#include <mma.h>

using namespace nvcuda;

#define N_CONS 10000
#define N_COLS 10000
#define NN     20000
#define NE     200000
#define NE2    (NE + NN)        // edges + self loops = 220000
#define NEG_SLOPE 0.2f

// ---------------- scratch (static __device__ globals; no allocs) ------------
__device__ float g_emb0[(size_t)NN * 128];
__device__ float g_xp1 [(size_t)NN * 1024];
__device__ float g_emb1[(size_t)NN * 1024];
__device__ float g_xp2 [(size_t)NN * 128];
__device__ float g_emb2[(size_t)NN * 128];
__device__ float g_asrc[(size_t)NN * 8];
__device__ float g_adst[(size_t)NN * 8];
__device__ int   g_deg[NN];
__device__ int   g_rowptr[NN + 1];
__device__ int   g_wpos[NN];
__device__ int   g_csrc[NE2];
__device__ int   g_part[64];
__device__ int   g_is64;

// ---------------- initial embedding ----------------------------------------
__global__ void k_embed(const float* __restrict__ cs, const float* __restrict__ co,
                        const float* __restrict__ nW, const float* __restrict__ nb,
                        const float* __restrict__ cW, const float* __restrict__ cb)
{
    int idx = blockIdx.x * blockDim.x + threadIdx.x;
    if (idx >= NN * 128) return;
    int n = idx >> 7, k = idx & 127;
    float s;
    if (n < N_CONS) {
        s = nb[k];
        const float* x = cs + (size_t)n * 4;
        const float* w = nW + (size_t)k * 8;
#pragma unroll
        for (int j = 0; j < 8; j++) s += x[j & 3] * w[j];
    } else {
        int m = n - N_CONS;
        s = cb[k];
        const float* x = co + (size_t)m * 8;
        const float* w = cW + (size_t)k * 16;
#pragma unroll
        for (int j = 0; j < 16; j++) s += x[j & 7] * w[j];
    }
    g_emb0[idx] = fmaxf(s, 0.f);
}

// ---------------- bf16 3-MMA compensated GEMM with register prefetch -------
// BM=128, BN=128, BK=32 (bf16). 8 warps 2(M)x4(N); warp tile 64x32.
// Smem row stride 40 bf16 (80B): 16B-aligned; fragment rows hit banks
// 20r mod 32 -> <=2-way conflicts. hi/lo split: acc += ah*bh + ah*bl + al*bh.
#define SST 40
__device__ __forceinline__ unsigned pk2(__nv_bfloat16 a, __nv_bfloat16 b)
{
    __nv_bfloat162 t; t.x = a; t.y = b;
    return *(unsigned*)&t;
}

template <bool RELU, bool BIAS>
__global__ __launch_bounds__(256, 1)
void k_gemm_tc(const float* __restrict__ A, const float* __restrict__ W,
               const float* __restrict__ bias, float* __restrict__ C,
               int M, int N, int K)
{
    __shared__ __align__(16) __nv_bfloat16 Ah[128 * SST];
    __shared__ __align__(16) __nv_bfloat16 Al[128 * SST];
    __shared__ __align__(16) __nv_bfloat16 Bh[128 * SST];
    __shared__ __align__(16) __nv_bfloat16 Bl[128 * SST];

    const int tid = threadIdx.x;
    const int wid = tid >> 5, lane = tid & 31;
    const int wm = wid >> 2, wn = wid & 3;      // 2 x 4 warp grid
    const int m0 = blockIdx.y * 128, n0 = blockIdx.x * 128;

    // per-thread tile slice: 2 groups of 8 contiguous k-values
    int row_[2], c8_[2];
#pragma unroll
    for (int l = 0; l < 2; l++) {
        int g = tid * 2 + l;
        row_[l] = g >> 2; c8_[l] = (g & 3) * 8;
    }

    float ax[2][8], bx[2][8];   // prefetch registers

    auto loadTiles = [&](int k0) {
#pragma unroll
        for (int l = 0; l < 2; l++) {
            const float* ap = A + (size_t)(m0 + row_[l]) * K + k0 + c8_[l];
            if (m0 + row_[l] < M) {
                float4 u = *(const float4*)ap, v = *(const float4*)(ap + 4);
                ax[l][0]=u.x; ax[l][1]=u.y; ax[l][2]=u.z; ax[l][3]=u.w;
                ax[l][4]=v.x; ax[l][5]=v.y; ax[l][6]=v.z; ax[l][7]=v.w;
            } else {
#pragma unroll
                for (int q = 0; q < 8; q++) ax[l][q] = 0.f;
            }
            const float* wp = W + (size_t)(n0 + row_[l]) * K + k0 + c8_[l];
            float4 u = *(const float4*)wp, v = *(const float4*)(wp + 4);
            bx[l][0]=u.x; bx[l][1]=u.y; bx[l][2]=u.z; bx[l][3]=u.w;
            bx[l][4]=v.x; bx[l][5]=v.y; bx[l][6]=v.z; bx[l][7]=v.w;
        }
    };
    auto storeTiles = [&]() {
#pragma unroll
        for (int l = 0; l < 2; l++) {
            __nv_bfloat16 h[8], lo[8];
#pragma unroll
            for (int q = 0; q < 8; q++) {
                h[q]  = __float2bfloat16(ax[l][q]);
                lo[q] = __float2bfloat16(ax[l][q] - __bfloat162float(h[q]));
            }
            *(uint4*)&Ah[row_[l] * SST + c8_[l]] =
                make_uint4(pk2(h[0],h[1]), pk2(h[2],h[3]),
                           pk2(h[4],h[5]), pk2(h[6],h[7]));
            *(uint4*)&Al[row_[l] * SST + c8_[l]] =
                make_uint4(pk2(lo[0],lo[1]), pk2(lo[2],lo[3]),
                           pk2(lo[4],lo[5]), pk2(lo[6],lo[7]));
#pragma unroll
            for (int q = 0; q < 8; q++) {
                h[q]  = __float2bfloat16(bx[l][q]);
                lo[q] = __float2bfloat16(bx[l][q] - __bfloat162float(h[q]));
            }
            *(uint4*)&Bh[row_[l] * SST + c8_[l]] =
                make_uint4(pk2(h[0],h[1]), pk2(h[2],h[3]),
                           pk2(h[4],h[5]), pk2(h[6],h[7]));
            *(uint4*)&Bl[row_[l] * SST + c8_[l]] =
                make_uint4(pk2(lo[0],lo[1]), pk2(lo[2],lo[3]),
                           pk2(lo[4],lo[5]), pk2(lo[6],lo[7]));
        }
    };

    wmma::fragment<wmma::accumulator, 16, 16, 16, float> acc[4][2];
#pragma unroll
    for (int i = 0; i < 4; i++)
#pragma unroll
        for (int j = 0; j < 2; j++) wmma::fill_fragment(acc[i][j], 0.f);

    loadTiles(0);
    for (int k0 = 0; k0 < K; k0 += 32) {
        storeTiles();
        __syncthreads();
        if (k0 + 32 < K) loadTiles(k0 + 32);   // LDGs overlap MMA below

#pragma unroll
        for (int kk = 0; kk < 32; kk += 16) {
            wmma::fragment<wmma::matrix_b, 16, 16, 16, __nv_bfloat16,
                           wmma::col_major> bh[2], bl[2];
#pragma unroll
            for (int j = 0; j < 2; j++) {
                int nb_ = wn * 32 + j * 16;
                wmma::load_matrix_sync(bh[j], &Bh[nb_ * SST + kk], SST);
                wmma::load_matrix_sync(bl[j], &Bl[nb_ * SST + kk], SST);
            }
#pragma unroll
            for (int i = 0; i < 4; i++) {
                int ma = wm * 64 + i * 16;
                wmma::fragment<wmma::matrix_a, 16, 16, 16, __nv_bfloat16,
                               wmma::row_major> ah, al;
                wmma::load_matrix_sync(ah, &Ah[ma * SST + kk], SST);
                wmma::load_matrix_sync(al, &Al[ma * SST + kk], SST);
#pragma unroll
                for (int j = 0; j < 2; j++) {
                    wmma::mma_sync(acc[i][j], ah, bh[j], acc[i][j]);
                    wmma::mma_sync(acc[i][j], ah, bl[j], acc[i][j]);
                    wmma::mma_sync(acc[i][j], al, bh[j], acc[i][j]);
                }
            }
        }
        __syncthreads();
    }

    // epilogue: frag -> smem (reuse Ah) -> global with optional bias/relu
    float* sb = (float*)Ah + wid * 256;
#pragma unroll
    for (int i = 0; i < 4; i++) {
#pragma unroll
        for (int j = 0; j < 2; j++) {
            wmma::store_matrix_sync(sb, acc[i][j], 16, wmma::mem_row_major);
            __syncwarp();
#pragma unroll
            for (int e = 0; e < 8; e++) {
                int idx = e * 32 + lane;
                int r = idx >> 4, c = idx & 15;
                int m = m0 + wm * 64 + i * 16 + r;
                int n = n0 + wn * 32 + j * 16 + c;
                if (m < M) {
                    float v = sb[idx];
                    if (BIAS) v += bias[n];
                    if (RELU) v = fmaxf(v, 0.f);
                    C[(size_t)m * N + n] = v;
                }
            }
            __syncwarp();
        }
    }
}

// ---------------- attention logits per node: a_src, a_dst ------------------
__global__ void k_att(const float* __restrict__ xp, const float* __restrict__ asv,
                      const float* __restrict__ adv, int H)
{
    int wid  = (blockIdx.x * blockDim.x + threadIdx.x) >> 5;
    int lane = threadIdx.x & 31;
    if (wid >= NN * H) return;
    int n = wid / H, h = wid % H;
    const float4* row = (const float4*)(xp  + ((size_t)n * H + h) * 128);
    const float4* as  = (const float4*)(asv + (size_t)h * 128);
    const float4* ad  = (const float4*)(adv + (size_t)h * 128);
    float4 v = row[lane], a = as[lane], b = ad[lane];
    float s = v.x*a.x + v.y*a.y + v.z*a.z + v.w*a.w;
    float d = v.x*b.x + v.y*b.y + v.z*b.z + v.w*b.w;
#pragma unroll
    for (int o = 16; o; o >>= 1) {
        s += __shfl_xor_sync(~0u, s, o);
        d += __shfl_xor_sync(~0u, d, o);
    }
    if (lane == 0) { g_asrc[n * H + h] = s; g_adst[n * H + h] = d; }
}

// ---------------- CSR build (by destination; includes self loops) ----------
__global__ void k_init(const void* ed)
{
    int i = blockIdx.x * blockDim.x + threadIdx.x;
    if (i == 0) {
        const int* p = (const int*)ed;
        int all0 = 1;
        for (int q = 0; q < 32; q++) all0 &= (p[2 * q + 1] == 0);
        g_is64 = all0;
    }
    if (i < NN) g_deg[i] = 1;   // self loop
}
__global__ void k_count(const void* ed)
{
    int e = blockIdx.x * blockDim.x + threadIdx.x;
    if (e >= NE) return;
    int d = g_is64 ? (int)((const long long*)ed)[NE + e]
                   : ((const int*)ed)[NE + e];
    atomicAdd(&g_deg[d], 1);
}
// ---- parallel 3-pass scan: 40 blocks x 512 ----
#define SCB 40
__global__ void k_scan1()
{
    int i = blockIdx.x * 512 + threadIdx.x;
    int lane = threadIdx.x & 31, w = threadIdx.x >> 5;
    int v = (i < NN) ? g_deg[i] : 0;
    int s = v;
#pragma unroll
    for (int o = 16; o; o >>= 1) s += __shfl_xor_sync(~0u, s, o);
    __shared__ int ws[16];
    if (lane == 0) ws[w] = s;
    __syncthreads();
    if (w == 0) {
        int t = (lane < 16) ? ws[lane] : 0;
#pragma unroll
        for (int o = 8; o; o >>= 1) t += __shfl_xor_sync(~0u, t, o);
        if (lane == 0) g_part[blockIdx.x] = t;
    }
}
__global__ void k_scan2()   // 1 warp: exclusive scan of 40 partials (2/lane)
{
    int lane = threadIdx.x;
    int a = (2 * lane < SCB)     ? g_part[2 * lane]     : 0;
    int b = (2 * lane + 1 < SCB) ? g_part[2 * lane + 1] : 0;
    int ps = a + b, incl = ps;
#pragma unroll
    for (int o = 1; o < 32; o <<= 1) {
        int t = __shfl_up_sync(~0u, incl, o);
        if (lane >= o) incl += t;
    }
    int excl = incl - ps;
    if (2 * lane < SCB)     g_part[2 * lane]     = excl;
    if (2 * lane + 1 < SCB) g_part[2 * lane + 1] = excl + a;
}
__global__ void k_scan3()
{
    int i = blockIdx.x * 512 + threadIdx.x;
    int lane = threadIdx.x & 31, w = threadIdx.x >> 5;
    int v = (i < NN) ? g_deg[i] : 0;
    int incl = v;
#pragma unroll
    for (int o = 1; o < 32; o <<= 1) {
        int t = __shfl_up_sync(~0u, incl, o);
        if (lane >= o) incl += t;
    }
    __shared__ int ws[16];
    if (lane == 31) ws[w] = incl;
    __syncthreads();
    if (w == 0 && lane < 16) {
        int t = ws[lane], s = t;
#pragma unroll
        for (int o = 1; o < 16; o <<= 1) {
            int u = __shfl_up_sync(0xffffu, s, o);
            if (lane >= o) s += u;
        }
        ws[lane] = s - t;
    }
    __syncthreads();
    int excl = g_part[blockIdx.x] + ws[w] + incl - v;
    if (i < NN) {
        g_rowptr[i] = excl;
        g_wpos[i]   = excl;
        if (i == NN - 1) g_rowptr[NN] = excl + v;
    }
}
__global__ void k_scatter(const void* ed)
{
    int e = blockIdx.x * blockDim.x + threadIdx.x;
    if (e >= NE2) return;
    int s, d;
    if (e < NE) {
        if (g_is64) { s = (int)((const long long*)ed)[e]; d = (int)((const long long*)ed)[NE + e]; }
        else        { s = ((const int*)ed)[e];            d = ((const int*)ed)[NE + e]; }
    } else {
        s = d = e - NE;
    }
    int p = atomicAdd(&g_wpos[d], 1);
    g_csrc[p] = s;
}

// ---------- fused segment softmax + aggregation (warp per dst,h) -----------
__global__ void k_softagg(const float* __restrict__ xp, const float* __restrict__ bias,
                          float* __restrict__ out, int H)
{
    int wid  = (blockIdx.x * blockDim.x + threadIdx.x) >> 5;
    int lane = threadIdx.x & 31;
    if (wid >= NN * H) return;
    int dst = wid / H, h = wid % H;
    int beg = g_rowptr[dst], end = g_rowptr[dst + 1];
    float ad = g_adst[dst * H + h];

    float m = -1e30f;
    for (int i = beg + lane; i < end; i += 32) {
        float e = g_asrc[g_csrc[i] * H + h] + ad;
        e = e > 0.f ? e : NEG_SLOPE * e;
        m = fmaxf(m, e);
    }
#pragma unroll
    for (int o = 16; o; o >>= 1) m = fmaxf(m, __shfl_xor_sync(~0u, m, o));

    float s = 0.f;
    for (int i = beg + lane; i < end; i += 32) {
        float e = g_asrc[g_csrc[i] * H + h] + ad;
        e = e > 0.f ? e : NEG_SLOPE * e;
        s += __expf(e - m);
    }
#pragma unroll
    for (int o = 16; o; o >>= 1) s += __shfl_xor_sync(~0u, s, o);
    float inv = 1.f / (s + 1e-16f);

    float4 acc = make_float4(0.f, 0.f, 0.f, 0.f);
    for (int i = beg; i < end; i++) {
        int   src = g_csrc[i];
        float e = g_asrc[src * H + h] + ad;          // broadcast load
        e = e > 0.f ? e : NEG_SLOPE * e;
        float a = __expf(e - m) * inv;
        float4 v = *(const float4*)(xp + ((size_t)src * H + h) * 128 + lane * 4);
        acc.x += a * v.x; acc.y += a * v.y; acc.z += a * v.z; acc.w += a * v.w;
    }
    const float* b = bias + (size_t)h * 128 + lane * 4;
    float4 r = make_float4(fmaxf(acc.x + b[0], 0.f), fmaxf(acc.y + b[1], 0.f),
                           fmaxf(acc.z + b[2], 0.f), fmaxf(acc.w + b[3], 0.f));
    *(float4*)(out + ((size_t)dst * H + h) * 128 + lane * 4) = r;
}

// ---------------- launch ----------------------------------------------------
extern "C" void kernel_launch(void* const* d_in, const int* in_sizes, int n_in,
                              void* d_out, int out_size)
{
    const float* cs    = (const float*)d_in[0];
    const float* co    = (const float*)d_in[1];
    const float* nW    = (const float*)d_in[2];
    const float* nb    = (const float*)d_in[3];
    const float* cW    = (const float*)d_in[4];
    const float* cb    = (const float*)d_in[5];
    const float* W1    = (const float*)d_in[6];
    const float* as1   = (const float*)d_in[7];
    const float* ad1   = (const float*)d_in[8];
    const float* b1    = (const float*)d_in[9];
    const float* W2    = (const float*)d_in[10];
    const float* as2   = (const float*)d_in[11];
    const float* ad2   = (const float*)d_in[12];
    const float* b2    = (const float*)d_in[13];
    const float* oW    = (const float*)d_in[14];
    const float* ob    = (const float*)d_in[15];
    const void*  edges = (const void*)d_in[16];
    float* out = (float*)d_out;

    float *p_emb0, *p_xp1, *p_emb1, *p_xp2, *p_emb2;
    cudaGetSymbolAddress((void**)&p_emb0, g_emb0);
    cudaGetSymbolAddress((void**)&p_xp1,  g_xp1);
    cudaGetSymbolAddress((void**)&p_emb1, g_emb1);
    cudaGetSymbolAddress((void**)&p_xp2,  g_xp2);
    cudaGetSymbolAddress((void**)&p_emb2, g_emb2);

    // CSR build (graph identical for both layers; flip only reorders edges)
    k_init<<<(NN + 255) / 256, 256>>>(edges);
    k_count<<<(NE + 255) / 256, 256>>>(edges);
    k_scan1<<<SCB, 512>>>();
    k_scan2<<<1, 32>>>();
    k_scan3<<<SCB, 512>>>();
    k_scatter<<<(NE2 + 255) / 256, 256>>>(edges);

    // initial node/column embeddings
    k_embed<<<(NN * 128 + 255) / 256, 256>>>(cs, co, nW, nb, cW, cb);

    // ----- GAT layer 1 (H=8, C=128) -----
    k_gemm_tc<false, false><<<dim3(8, (NN + 127) / 128), 256>>>(
        p_emb0, W1, nullptr, p_xp1, NN, 1024, 128);
    k_att<<<(NN * 8) / 8, 256>>>(p_xp1, as1, ad1, 8);
    k_softagg<<<(NN * 8) / 8, 256>>>(p_xp1, b1, p_emb1, 8);

    // ----- GAT layer 2 (H=1, C=128) -----
    k_gemm_tc<false, false><<<dim3(1, (NN + 127) / 128), 256>>>(
        p_emb1, W2, nullptr, p_xp2, NN, 128, 1024);
    k_att<<<(NN * 1 + 7) / 8, 256>>>(p_xp2, as2, ad2, 1);
    k_softagg<<<(NN * 1 + 7) / 8, 256>>>(p_xp2, b2, p_emb2, 1);

    // ----- logits = emb2[-N_COLS:] @ out_W^T + out_b -----
    k_gemm_tc<false, true><<<dim3(1, (N_COLS + 127) / 128), 256>>>(
        p_emb2 + (size_t)N_CONS * 128, oW, ob, out, N_COLS, 128, 128);
}